// round 2
// baseline (speedup 1.0000x reference)
#include <cuda_runtime.h>
#include <cuda_bf16.h>
#include <math.h>

// Problem constants
constexpr int Bsz = 4;
constexpr int L   = 4096;
constexpr int D   = 1024;
constexpr int H   = 16;
constexpr int G   = 8;
constexpr int LG  = L / G;     // 512
constexpr int DH  = D / H;     // 64
constexpr int M_TOK = Bsz * L; // 16384

// Scratch (allocation-free: static __device__ globals)
__device__ float g_qkv[(size_t)M_TOK * 3 * D];   // [B*L, 3D]
__device__ float g_att[(size_t)M_TOK * D];       // [B*L, D]

// ---------------------------------------------------------------------------
// SGEMM: C[M,N] = A[M,K] * B[N,K]^T (+ bias[n]), all row-major fp32.
// 128x128 tile, BK=16, 256 threads, 8x8 micro-tile.
// Assumes M%128==0, N%128==0, K%16==0 (true for all our shapes).
// ---------------------------------------------------------------------------
__global__ __launch_bounds__(256) void sgemm_nt(const float* __restrict__ A,
                                                const float* __restrict__ B,
                                                const float* __restrict__ bias,
                                                float* __restrict__ C,
                                                int M, int N, int K)
{
    __shared__ float As[16][128];
    __shared__ float Bs[16][128];

    const int tid = threadIdx.x;
    const int bm = blockIdx.y * 128;
    const int bn = blockIdx.x * 128;

    const int lrow = tid >> 2;          // 0..63 (load rows lrow, lrow+64)
    const int lc4  = (tid & 3) * 4;     // 0,4,8,12
    const int trow = (tid >> 4) * 8;    // compute rows
    const int tcol = (tid & 15) * 8;    // compute cols

    const float* Ap = A + (size_t)(bm + lrow) * K + lc4;
    const float* Bp = B + (size_t)(bn + lrow) * K + lc4;

    float acc[8][8];
    #pragma unroll
    for (int i = 0; i < 8; i++)
        #pragma unroll
        for (int j = 0; j < 8; j++) acc[i][j] = 0.f;

    for (int k0 = 0; k0 < K; k0 += 16) {
        #pragma unroll
        for (int r = 0; r < 2; r++) {
            float4 a = *(const float4*)(Ap + (size_t)r * 64 * K + k0);
            As[lc4 + 0][lrow + r * 64] = a.x;
            As[lc4 + 1][lrow + r * 64] = a.y;
            As[lc4 + 2][lrow + r * 64] = a.z;
            As[lc4 + 3][lrow + r * 64] = a.w;
            float4 b = *(const float4*)(Bp + (size_t)r * 64 * K + k0);
            Bs[lc4 + 0][lrow + r * 64] = b.x;
            Bs[lc4 + 1][lrow + r * 64] = b.y;
            Bs[lc4 + 2][lrow + r * 64] = b.z;
            Bs[lc4 + 3][lrow + r * 64] = b.w;
        }
        __syncthreads();

        #pragma unroll
        for (int k = 0; k < 16; k++) {
            float a[8], b[8];
            *(float4*)&a[0] = *(const float4*)&As[k][trow];
            *(float4*)&a[4] = *(const float4*)&As[k][trow + 4];
            *(float4*)&b[0] = *(const float4*)&Bs[k][tcol];
            *(float4*)&b[4] = *(const float4*)&Bs[k][tcol + 4];
            #pragma unroll
            for (int i = 0; i < 8; i++)
                #pragma unroll
                for (int j = 0; j < 8; j++)
                    acc[i][j] = fmaf(a[i], b[j], acc[i][j]);
        }
        __syncthreads();
    }

    #pragma unroll
    for (int i = 0; i < 8; i++) {
        const size_t row = (size_t)(bm + trow + i) * N + bn + tcol;
        #pragma unroll
        for (int j = 0; j < 8; j += 4) {
            float4 v;
            v.x = acc[i][j + 0];
            v.y = acc[i][j + 1];
            v.z = acc[i][j + 2];
            v.w = acc[i][j + 3];
            if (bias) {
                v.x += bias[bn + tcol + j + 0];
                v.y += bias[bn + tcol + j + 1];
                v.z += bias[bn + tcol + j + 2];
                v.w += bias[bn + tcol + j + 3];
            }
            *(float4*)&C[row + j] = v;
        }
    }
}

// ---------------------------------------------------------------------------
// Blocked attention. One CTA = one (b,h,g) block x 32-query tile.
// Full 32x512 score rows in smem; no online softmax needed.
// grid.x = B*H*G*16 = 8192, 256 threads.
// ---------------------------------------------------------------------------
constexpr int S_LD  = 513;   // padded row stride for S
constexpr int Q_LD  = 65;
constexpr int KV_LD = 65;
constexpr int ATTN_SMEM = (32 * S_LD + 32 * Q_LD + 64 * KV_LD) * 4;  // 90624 B

__global__ __launch_bounds__(256) void attn_kernel(const float* __restrict__ qkv,
                                                   float* __restrict__ att)
{
    extern __shared__ float sm[];
    float* S   = sm;                    // [32][513]
    float* Qs  = S + 32 * S_LD;         // [32][65]
    float* KVs = Qs + 32 * Q_LD;        // [64][65]

    const int tid = threadIdx.x;
    const int idx = blockIdx.x;
    const int qt  = idx & 15;           // q-tile within block
    const int bhg = idx >> 4;
    const int g = bhg & 7;
    const int h = (bhg >> 3) & 15;
    const int b = bhg >> 7;

    const int pos0  = g * LG;
    const int qpos0 = pos0 + qt * 32;
    const float scale = 0.125f;         // 64^-0.5

    const float* qbase = qkv + ((size_t)(b * L + qpos0) * (3 * D)) + h * DH;
    const float* kbase = qkv + ((size_t)(b * L + pos0)  * (3 * D)) + D + h * DH;
    const float* vbase = kbase + D;

    // Load Q tile: 32 rows x 64 -> 512 float4 -> 2 per thread
    #pragma unroll
    for (int i = 0; i < 2; i++) {
        int f = tid + i * 256;
        int row = f >> 4;
        int c4 = (f & 15) * 4;
        float4 v = *(const float4*)(qbase + (size_t)row * (3 * D) + c4);
        float* dst = Qs + row * Q_LD + c4;
        dst[0] = v.x; dst[1] = v.y; dst[2] = v.z; dst[3] = v.w;
    }

    // Micro-tile mapping: 4 rows x 2 cols per thread
    const int lane = tid & 31;
    const int wid  = tid >> 5;
    const int r0 = wid * 4;             // rows r0..r0+3
    const int c0 = lane * 2;            // cols c0, c0+1

    // ---- Pass 1: S = scale * Q K^T ----
    for (int ck = 0; ck < 8; ck++) {
        __syncthreads();
        #pragma unroll
        for (int i = 0; i < 4; i++) {
            int f = tid + i * 256;
            int row = f >> 4;
            int c4 = (f & 15) * 4;
            float4 v = *(const float4*)(kbase + (size_t)(ck * 64 + row) * (3 * D) + c4);
            float* dst = KVs + row * KV_LD + c4;
            dst[0] = v.x; dst[1] = v.y; dst[2] = v.z; dst[3] = v.w;
        }
        __syncthreads();

        float acc[4][2] = {};
        #pragma unroll
        for (int d = 0; d < 64; d++) {
            float k0 = KVs[c0 * KV_LD + d];
            float k1 = KVs[(c0 + 1) * KV_LD + d];
            #pragma unroll
            for (int i = 0; i < 4; i++) {
                float q = Qs[(r0 + i) * Q_LD + d];
                acc[i][0] = fmaf(q, k0, acc[i][0]);
                acc[i][1] = fmaf(q, k1, acc[i][1]);
            }
        }
        #pragma unroll
        for (int i = 0; i < 4; i++) {
            S[(r0 + i) * S_LD + ck * 64 + c0]     = acc[i][0] * scale;
            S[(r0 + i) * S_LD + ck * 64 + c0 + 1] = acc[i][1] * scale;
        }
    }
    __syncthreads();

    // ---- Pass 2: row softmax (warp w handles rows 4w..4w+3) ----
    for (int r = wid * 4; r < wid * 4 + 4; r++) {
        float* row = S + r * S_LD;
        float m = -INFINITY;
        for (int j = lane; j < 512; j += 32) m = fmaxf(m, row[j]);
        #pragma unroll
        for (int o = 16; o; o >>= 1) m = fmaxf(m, __shfl_xor_sync(0xffffffffu, m, o));
        float s = 0.f;
        for (int j = lane; j < 512; j += 32) {
            float e = __expf(row[j] - m);
            row[j] = e;
            s += e;
        }
        #pragma unroll
        for (int o = 16; o; o >>= 1) s += __shfl_xor_sync(0xffffffffu, s, o);
        float inv = 1.0f / s;
        for (int j = lane; j < 512; j += 32) row[j] *= inv;
    }
    __syncthreads();

    // ---- Pass 3: O = P V ----
    float oacc[4][2] = {};
    for (int ck = 0; ck < 8; ck++) {
        __syncthreads();
        #pragma unroll
        for (int i = 0; i < 4; i++) {
            int f = tid + i * 256;
            int row = f >> 4;
            int c4 = (f & 15) * 4;
            float4 v = *(const float4*)(vbase + (size_t)(ck * 64 + row) * (3 * D) + c4);
            float* dst = KVs + row * KV_LD + c4;
            dst[0] = v.x; dst[1] = v.y; dst[2] = v.z; dst[3] = v.w;
        }
        __syncthreads();

        #pragma unroll
        for (int kk = 0; kk < 64; kk++) {
            float v0 = KVs[kk * KV_LD + c0];
            float v1 = KVs[kk * KV_LD + c0 + 1];
            #pragma unroll
            for (int i = 0; i < 4; i++) {
                float p = S[(r0 + i) * S_LD + ck * 64 + kk];
                oacc[i][0] = fmaf(p, v0, oacc[i][0]);
                oacc[i][1] = fmaf(p, v1, oacc[i][1]);
            }
        }
    }

    #pragma unroll
    for (int i = 0; i < 4; i++) {
        float* dst = att + ((size_t)(b * L + qpos0 + r0 + i) * D) + h * DH + c0;
        dst[0] = oacc[i][0];
        dst[1] = oacc[i][1];
    }
}

// ---------------------------------------------------------------------------
extern "C" void kernel_launch(void* const* d_in, const int* in_sizes, int n_in,
                              void* d_out, int out_size)
{
    const float* x     = (const float*)d_in[0];   // [B,L,D]
    const float* w_qkv = (const float*)d_in[1];   // [3D, D]
    const float* w_out = (const float*)d_in[2];   // [D, D]
    const float* b_out = (const float*)d_in[3];   // [D]
    float* out = (float*)d_out;                   // [B,L,D]

    float* qkv_ptr = nullptr;
    float* att_ptr = nullptr;
    cudaGetSymbolAddress((void**)&qkv_ptr, g_qkv);
    cudaGetSymbolAddress((void**)&att_ptr, g_att);

    cudaFuncSetAttribute(attn_kernel, cudaFuncAttributeMaxDynamicSharedMemorySize,
                         ATTN_SMEM);

    dim3 blk(256);
    // 1) QKV projection: [16384,1024] x [3072,1024]^T -> [16384,3072]
    sgemm_nt<<<dim3(3 * D / 128, M_TOK / 128), blk>>>(x, w_qkv, nullptr, qkv_ptr,
                                                      M_TOK, 3 * D, D);
    // 2) Blocked attention
    attn_kernel<<<Bsz * H * G * 16, blk, ATTN_SMEM>>>(qkv_ptr, att_ptr);
    // 3) Output projection + bias: [16384,1024] x [1024,1024]^T -> out
    sgemm_nt<<<dim3(D / 128, M_TOK / 128), blk>>>(att_ptr, w_out, b_out, out,
                                                  M_TOK, D, D);
}